// round 16
// baseline (speedup 1.0000x reference)
#include <cuda_runtime.h>
#include <stdint.h>

#define FEAT   256
#define NCLS   100
#define KSEL   16
#define NMAX   100000
#define BMAX   512
#define BTHREADS 256

// Scratch (no cudaMalloc allowed).
__device__ float g_sum[NMAX + BMAX];
__device__ int   g_cls[BMAX];

// ---------------------------------------------------------------------------
// Kernel A: row sums in LLVM/aarch64 VF=4 x IC=2 order (PROVEN R15, rel_err=0):
//   a0 += x[8i..8i+3], a1 += x[8i+4..8i+7] (i ascending), c = a0+a1,
//   tot = (c0+c1)+(c2+c3).
// R15 ncu: 29.9us, DRAM 44%, issue 4% -> latency-bound (ptxas reused load
// regs, MLP~4). This version stages 8 independent LDG.128 per step to raise
// MLP; the __fadd_rn chain order is BIT-IDENTICAL to R15.
// ---------------------------------------------------------------------------
__global__ void row_sums_kernel(const float* __restrict__ x,
                                const float* __restrict__ features,
                                int N, int B) {
    int r = blockIdx.x * blockDim.x + threadIdx.x;
    int rows = N + B;
    if (r >= rows) return;

    const float* src = (r < N) ? (features + (size_t)r * FEAT)
                               : (x + (size_t)(r - N) * FEAT);
    const float4* v = (const float4*)src;

    float4 a0 = make_float4(0.f, 0.f, 0.f, 0.f);
    float4 a1 = a0;
    #pragma unroll
    for (int blk = 0; blk < 8; blk++) {            // 8 batches of 8 float4
        float4 q[8];
        #pragma unroll
        for (int k = 0; k < 8; k++) q[k] = v[blk * 8 + k];   // 8 LDGs in flight
        #pragma unroll
        for (int k = 0; k < 8; k += 2) {           // same accumulation order
            a0.x = __fadd_rn(a0.x, q[k].x); a0.y = __fadd_rn(a0.y, q[k].y);
            a0.z = __fadd_rn(a0.z, q[k].z); a0.w = __fadd_rn(a0.w, q[k].w);
            a1.x = __fadd_rn(a1.x, q[k+1].x); a1.y = __fadd_rn(a1.y, q[k+1].y);
            a1.z = __fadd_rn(a1.z, q[k+1].z); a1.w = __fadd_rn(a1.w, q[k+1].w);
        }
    }
    float c0 = __fadd_rn(a0.x, a1.x);
    float c1 = __fadd_rn(a0.y, a1.y);
    float c2 = __fadd_rn(a0.z, a1.z);
    float c3 = __fadd_rn(a0.w, a1.w);
    g_sum[r] = __fadd_rn(__fadd_rn(c0, c1), __fadd_rn(c2, c3));
}

// ---------------------------------------------------------------------------
// Kernel B: one block per query; per-thread top-16 in REGISTERS (R15 post-
// mortem: the smem lists had a 128B stride -> 32-way bank conflicts on every
// list access -> ~500us). Insert and merge use only statically-indexed,
// predicated unrolled loops (no local-mem spill).
// Packed key (key_bits<<32)|idx: uint64 min == lexicographic (dist,index)
// min == top_k tie-break. key = d*d+1e-6 order-equivalent to sqrt(d*d+1e-6).
// ---------------------------------------------------------------------------
__global__ void knn_vote_kernel(const int* __restrict__ labels32, int N) {
    __shared__ unsigned long long red8[8];
    __shared__ int counts[NCLS];
    __shared__ int s_stride;                       // 1 = int32, 2 = int64

    int b   = blockIdx.x;
    int tid = threadIdx.x;
    float sx = g_sum[N + b];

    if (tid < NCLS) counts[tid] = 0;

    // Label dtype probe: warp 0 checks odd words 1,3,...,63 (in-bounds both ways).
    if (tid < 32) {
        int v = labels32[2 * tid + 1];
        unsigned any = __ballot_sync(0xffffffffu, v != 0);
        if (tid == 0) s_stride = (any == 0u) ? 2 : 1;
    }

    unsigned long long my[KSEL];                   // register-resident
    #pragma unroll
    for (int j = 0; j < KSEL; j++) my[j] = ~0ull;
    unsigned long long worst = ~0ull;

    for (int i = tid; i < N; i += BTHREADS) {
        float d  = __fadd_rn(sx, -g_sum[i]);
        float ky = __fadd_rn(__fmul_rn(d, d), 1e-6f);
        unsigned long long pk =
            ((unsigned long long)__float_as_uint(ky) << 32) | (unsigned)i;
        if (pk < worst) {
            // Replace FIRST slot equal to worst (unique among real entries;
            // 'done' guard handles the all-~0ull fill phase).
            bool done = false;
            #pragma unroll
            for (int j = 0; j < KSEL; j++) {
                if (!done && my[j] == worst) { my[j] = pk; done = true; }
            }
            // Recompute worst (15-op max tree, predicated/unrolled).
            unsigned long long w = my[0];
            #pragma unroll
            for (int j = 1; j < KSEL; j++) w = (my[j] > w) ? my[j] : w;
            worst = w;
        }
    }
    __syncthreads();
    int lstride = s_stride;

    // 16-round global merge: block-min over per-thread register lists;
    // winner removes its entry by predicated match (pk values unique).
    for (int r = 0; r < KSEL; r++) {
        unsigned long long lm = my[0];
        #pragma unroll
        for (int j = 1; j < KSEL; j++) lm = (my[j] < lm) ? my[j] : lm;

        unsigned long long wmin = lm;
        #pragma unroll
        for (int off = 16; off; off >>= 1) {
            unsigned long long u = __shfl_xor_sync(0xffffffffu, wmin, off);
            wmin = (u < wmin) ? u : wmin;
        }
        if ((tid & 31) == 0) red8[tid >> 5] = wmin;
        __syncthreads();
        unsigned long long m = red8[0];
        #pragma unroll
        for (int j = 1; j < 8; j++) { unsigned long long u = red8[j]; m = (u < m) ? u : m; }

        if (lm == m) {                             // exactly one owner
            #pragma unroll
            for (int j = 0; j < KSEL; j++) if (my[j] == m) my[j] = ~0ull;
        }
        if (tid == 0) {
            int idx = (int)(unsigned)(m & 0xffffffffull);
            int lab = labels32[(size_t)idx * lstride];   // low word if int64
            if (lab < 0 || lab >= NCLS) lab = 0;          // hard clamp
            counts[lab]++;
        }
        __syncthreads();
    }

    // Vote: first max (== jnp.argmax) -> strict '>' scan.
    if (tid == 0) {
        int best = 0, bc = -1;
        #pragma unroll 4
        for (int c = 0; c < NCLS; c++) {
            int v = counts[c];
            if (v > bc) { bc = v; best = c; }
        }
        g_cls[b] = best;
    }
}

// ---------------------------------------------------------------------------
// Kernel C: out[i][j] = (float)cls[j]. Output buffer is FLOAT32 (proven R8).
// ---------------------------------------------------------------------------
__global__ void fill_out_kernel(float* __restrict__ out, int B) {
    int j = threadIdx.x;
    int i = blockIdx.x;
    if (j < B) out[(size_t)i * B + j] = (float)g_cls[j];
}

extern "C" void kernel_launch(void* const* d_in, const int* in_sizes, int n_in,
                              void* d_out, int out_size) {
    const float* x        = (const float*)d_in[0];
    const float* features = (const float*)d_in[1];
    const int*   labels32 = (const int*)d_in[2];
    int B = in_sizes[0] / FEAT;   // 512
    int N = in_sizes[2];          // 100000

    int rows = N + B;
    row_sums_kernel<<<(rows + 255) / 256, 256>>>(x, features, N, B);
    knn_vote_kernel<<<B, BTHREADS>>>(labels32, N);
    fill_out_kernel<<<B, B>>>((float*)d_out, B);
}